// round 17
// baseline (speedup 1.0000x reference)
#include <cuda_runtime.h>
#include <cuda_bf16.h>

// Problem constants (fixed by the reference)
#define WF 512.0f
#define HF 512.0f
#define NGMAX 2048
#define TILES_X 32
#define TILES_Y 32
#define TILES (TILES_X * TILES_Y)
#define TILE_W 16.0f
#define PCAP 256              // per-tile pixel capacity (mean 64, max ~110)
#define MWORDS 64             // 2048 bits per tile mask
#define SCAP 320              // staged coefficients per tile (max well below)
#define TPB_PREP 256
#define TPB_SPLAT 128

// Per-gaussian packed coefficients: 2 x float4: [P,Q,R,mx] [my,cr,cg,cb]
// (P,Q,R pre-scaled by -log2(e) so exp is a single ex2)
__device__ float4 g_coef[NGMAX * 2];
// Per-tile gaussian bitmask (2048 bits). atomicOr is commutative+idempotent
// -> deterministic. Statically zero; splat re-zeroes after reading.
__device__ unsigned g_gmask[TILES * MWORDS];
__device__ int g_pcnt[TILES];             // statically zero; re-zeroed by splat
__device__ float4 g_pxyi[TILES * PCAP];   // [x, y, bitcast(pixel idx), 0]

__device__ __forceinline__ float ex2(float x) {
    float r; asm("ex2.approx.ftz.f32 %0,%1;" : "=f"(r) : "f"(x)); return r;
}
__device__ __forceinline__ float rcp(float x) {
    float r; asm("rcp.approx.ftz.f32 %0,%1;" : "=f"(r) : "f"(x)); return r;
}
__device__ __forceinline__ float fexp(float x) { return ex2(x * 1.4426950408889634f); }
__device__ __forceinline__ float ftanh(float x) {
    float e = ex2(x * 2.8853900817779268f);   // e^{2x}
    return 1.0f - 2.0f * rcp(e + 1.0f);
}
__device__ __forceinline__ float fsigm(float x) {
    return rcp(1.0f + fexp(-x));
}

// ---------------------------------------------------------------------------
// Kernel 1 (identical to round-15 winner): warp w owns gaussian w
// (lane-parallel tile-box binning kills the big-gaussian straggler);
// every thread bins exactly 1 pixel.
// Cull: |v| > 4/minS gives w < e^-16; dropped mass <= 2048*1.1e-7 ~ 2e-4 abs.
// ---------------------------------------------------------------------------
__global__ void __launch_bounds__(TPB_PREP) prep_kernel(const float* __restrict__ rgb,
                                                        const float* __restrict__ mu,
                                                        const float* __restrict__ scale,
                                                        const float* __restrict__ angle,
                                                        const float* __restrict__ x,
                                                        int N, int B) {
    int gtid = blockIdx.x * TPB_PREP + threadIdx.x;
    int gi   = gtid >> 5;          // gaussian owned by this warp
    int lane = gtid & 31;

    // pixel-binning load issued FIRST (independent of everything below)
    float2 xy = make_float2(0.f, 0.f);
    if (gtid < B) xy = ((const float2*)x)[gtid];

    if (gi < N) {
        const float MU_BORDER = 1.05f;
        const float PI_APPROX = 3.1416f;
        const float S_MIN = 1.0f / 30.0f;
        const float S_MAX = 1.0f / 0.75f;
        const float LOG2E = 1.4426950408889634f;

        // warp-uniform loads (broadcast), redundantly computed by all lanes
        float mpx = (ftanh(mu[2 * gi + 0]) * MU_BORDER + 1.0f) * 0.5f * WF;
        float mpy = (ftanh(mu[2 * gi + 1]) * MU_BORDER + 1.0f) * 0.5f * HF;

        float al = ftanh(angle[gi]) * PI_APPROX;
        float c, s;
        __sincosf(al, &s, &c);

        float S0 = fsigm(scale[2 * gi + 0]) * (S_MAX - S_MIN) + S_MIN;
        float S1 = fsigm(scale[2 * gi + 1]) * (S_MAX - S_MIN) + S_MIN;

        float a = S0 * c, b = -S0 * s;
        float e = S1 * s, f = S1 * c;

        float P = -LOG2E * (a * a + e * e);
        float Q = -LOG2E * 2.0f * (a * b + e * f);
        float R = -LOG2E * (b * b + f * f);

        if (lane == 0) {
            float cr = fsigm(rgb[3 * gi + 0]);
            float cg = fsigm(rgb[3 * gi + 1]);
            float cb = fsigm(rgb[3 * gi + 2]);
            g_coef[2 * gi]     = make_float4(P, Q, R, mpx);
            g_coef[2 * gi + 1] = make_float4(mpy, cr, cg, cb);
        }

        // ---- lane-parallel gaussian -> tile bitmask binning ----
        float Smin = fminf(S0, S1);
        float r = 4.0f / Smin;                 // w = e^-16 level set
        float r2 = r * r * 1.0001f + 1e-2f;

        int txmin = max(0, (int)((mpx - r) * (1.0f / TILE_W)));
        int txmax = min(TILES_X - 1, (int)((mpx + r) * (1.0f / TILE_W)));
        int tymin = max(0, (int)((mpy - r) * (1.0f / TILE_W)));
        int tymax = min(TILES_Y - 1, (int)((mpy + r) * (1.0f / TILE_W)));
        int bw = txmax - txmin + 1;
        int bh = tymax - tymin + 1;
        int nbox = bw * bh;

        unsigned bit = 1u << (gi & 31);
        int word = gi >> 5;

        for (int idx = lane; idx < nbox; idx += 32) {
            int ty = tymin + idx / bw;
            int tx = txmin + idx - (idx / bw) * bw;
            float x0 = tx * TILE_W, x1 = x0 + TILE_W;
            float y0 = ty * TILE_W, y1 = y0 + TILE_W;
            float dx = fmaxf(fmaxf(x0 - mpx, mpx - x1), 0.0f);
            float dy = fmaxf(fmaxf(y0 - mpy, mpy - y1), 0.0f);
            if (dx * dx + dy * dy <= r2) {
                atomicOr(&g_gmask[(ty * TILES_X + tx) * MWORDS + word], bit);
            }
        }
    }

    // ---- pixel binning: 1 pixel per thread; single 16B record ----
    if (gtid < B) {
        int tx = (int)(xy.x * (1.0f / TILE_W));
        int ty = (int)(xy.y * (1.0f / TILE_W));
        tx = min(max(tx, 0), TILES_X - 1);
        ty = min(max(ty, 0), TILES_Y - 1);
        int t = ty * TILES_X + tx;
        int slot = atomicAdd(&g_pcnt[t], 1);
        if (slot < PCAP) {
            g_pxyi[t * PCAP + slot] =
                make_float4(xy.x, xy.y, __int_as_float(gtid), 0.0f);
        }
    }
}

// ---------------------------------------------------------------------------
// Kernel 2: TWO tiles per block (grid 512 x 128 threads) to halve the
// per-block prologue count. Warps 0-1 build tile A's list, warps 2-3 tile
// B's, in parallel (ascending-index prefix expansion per tile ->
// deterministic). All 128 threads then stage both tiles' coefficients and
// run both pixel loops in fixed tile order A,B.
// Re-zeroes g_gmask and g_pcnt for the next graph replay.
// ---------------------------------------------------------------------------
__global__ void __launch_bounds__(TPB_SPLAT) splat_tiled(float* __restrict__ out) {
    __shared__ unsigned short slist[2][NGMAX];   // 8 KB (full-safety capacity)
    __shared__ float4 scoef[2][SCAP][2];         // 20 KB
    __shared__ int wtot[4];
    __shared__ int s_pc[2];

    const int tA = 2 * blockIdx.x;
    const int tB = tA + 1;
    const int tid = threadIdx.x;
    const int wid = tid >> 5;
    const int lane = tid & 31;
    const int sel = wid >> 1;              // 0 -> tile A, 1 -> tile B

    // ---- independent top-of-kernel loads ----
    if (tid < 2) {
        int tt = tid ? tB : tA;
        s_pc[tid] = min(g_pcnt[tt], PCAP);
        g_pcnt[tt] = 0;                    // reset for next graph replay
    }
    const int myt = sel ? tB : tA;
    const int wrd = tid - sel * MWORDS;    // word index within my tile (0..63)
    unsigned m = g_gmask[myt * MWORDS + wrd];
    g_gmask[myt * MWORDS + wrd] = 0;       // reset for next graph replay

    // ---- per-tile list build: 2 warps per tile, ascending index order ----
    int c = __popc(m);
    int inc = c;
#pragma unroll
    for (int d = 1; d < 32; d <<= 1) {
        int v = __shfl_up_sync(0xffffffffu, inc, d);
        if (lane >= d) inc += v;
    }
    if (lane == 31) wtot[wid] = inc;
    __syncthreads();
    const int totA = wtot[0] + wtot[1];
    const int totB = wtot[2] + wtot[3];

    {
        int off = inc - c + ((wid & 1) ? wtot[sel * 2] : 0);
        unsigned mm = m;
        int o = off;
        int base = wrd * 32;
        while (mm) {
            int b = __ffs(mm) - 1;
            slist[sel][o++] = (unsigned short)(base + b);
            mm &= mm - 1;
        }
    }
    __syncthreads();

    // ---- cooperative coefficient staging for both tiles ----
    const int ncA = min(totA, SCAP);
    const int ncB = min(totB, SCAP);
    for (int j = tid; j < ncA; j += TPB_SPLAT) {
        int gi = slist[0][j];
        scoef[0][j][0] = g_coef[2 * gi];
        scoef[0][j][1] = g_coef[2 * gi + 1];
    }
    for (int j = tid; j < ncB; j += TPB_SPLAT) {
        int gi = slist[1][j];
        scoef[1][j][0] = g_coef[2 * gi];
        scoef[1][j][1] = g_coef[2 * gi + 1];
    }
    __syncthreads();

    // ---- pixel loops: tiles in fixed order A then B (deterministic) ----
#pragma unroll
    for (int tt = 0; tt < 2; tt++) {
        const int t = tt ? tB : tA;
        const int pcnt = s_pc[tt];
        const int nc = tt ? ncB : ncA;
        const int total = tt ? totB : totA;

        for (int i = tid; i < pcnt; i += TPB_SPLAT) {
            float4 rec = g_pxyi[t * PCAP + i];
            float px = rec.x, py = rec.y;

            float ar = 0.f, ag = 0.f, ab = 0.f;

#pragma unroll 4
            for (int j = 0; j < nc; j++) {
                float4 cA = scoef[tt][j][0];      // P,Q,R,mx
                float4 cB = scoef[tt][j][1];      // my,cr,cg,cb
                float vx = px - cA.w;
                float vy = py - cB.x;
                float q = fmaf(vx, fmaf(cA.y, vy, cA.x * vx), (cA.z * vy) * vy);
                float wgt = ex2(q);
                ar = fmaf(wgt, cB.y, ar);
                ag = fmaf(wgt, cB.z, ag);
                ab = fmaf(wgt, cB.w, ab);
            }
            // overflow path (statistically never; preserves correctness)
            for (int j = SCAP; j < total; j++) {
                int gi = slist[tt][j];
                float4 cA = g_coef[2 * gi];
                float4 cB = g_coef[2 * gi + 1];
                float vx = px - cA.w;
                float vy = py - cB.x;
                float q = fmaf(vx, fmaf(cA.y, vy, cA.x * vx), (cA.z * vy) * vy);
                float wgt = ex2(q);
                ar = fmaf(wgt, cB.y, ar);
                ag = fmaf(wgt, cB.z, ag);
                ab = fmaf(wgt, cB.w, ab);
            }

            int pix = __float_as_int(rec.z);
            out[3 * pix + 0] = ar;
            out[3 * pix + 1] = ag;
            out[3 * pix + 2] = ab;
        }
    }
}

// ---------------------------------------------------------------------------
// Launch: inputs in metadata order: x[B,2], rgb[N,3], mu[N,2], scale[N,2], angle[N]
// ---------------------------------------------------------------------------
extern "C" void kernel_launch(void* const* d_in, const int* in_sizes, int n_in,
                              void* d_out, int out_size) {
    const float* x     = (const float*)d_in[0];
    const float* rgb   = (const float*)d_in[1];
    const float* mu    = (const float*)d_in[2];
    const float* scale = (const float*)d_in[3];
    const float* angle = (const float*)d_in[4];
    float* out = (float*)d_out;

    int N = in_sizes[4];          // 2048
    int B = in_sizes[0] / 2;      // 65536

    prep_kernel<<<B / TPB_PREP, TPB_PREP>>>(rgb, mu, scale, angle, x, N, B);
    splat_tiled<<<TILES / 2, TPB_SPLAT>>>(out);
}